// round 1
// baseline (speedup 1.0000x reference)
#include <cuda_runtime.h>
#include <math.h>

// ---------------- problem constants ----------------
#define IMG   256
#define PATCH 7
#define PP    49           // patch pixels
#define WN    37           // search window
#define NOFF  (WN*WN)      // 1369
#define INC   18           // WN/2
#define RPAD  21           // PATCH/2 + WN/2
#define HP    298          // IMG + 2*RPAD
#define PG    292          // patch-grid size = IMG + WN - 1
#define LTOT  (PG*PG)      // 85264
#define NCH   64           // centers per dim  (IMG/4)
#define NC    4096         // total centers
#define M1    18
#define M2    55
#define CENTER_OFF (INC*WN + INC)   // 684

// ---------------- device scratch (no allocs allowed) ----------------
__device__ float g_pad_y[HP*HP];
__device__ float g_pad_x[HP*HP];
__device__ float g_den1[IMG*IMG];
__device__ int   g_idx1[NC*M1];
__device__ int   g_idx2[NC*M2];
__device__ float g_xsum[PP*LTOT];
__device__ float g_wsum[LTOT];

// ---------------- reflect pad 256 -> 298 ----------------
__global__ void pad_input_kernel(const float* __restrict__ src, int use_den1) {
    int t = blockIdx.x * blockDim.x + threadIdx.x;
    if (t >= HP*HP) return;
    int y = t / HP - RPAD, x = t % HP - RPAD;
    y = (y < 0) ? -y : ((y > IMG-1) ? 2*(IMG-1) - y : y);
    x = (x < 0) ? -x : ((x > IMG-1) ? 2*(IMG-1) - x : x);
    float v = use_den1 ? g_den1[y*IMG + x] : src[y*IMG + x];
    if (use_den1) g_pad_x[t] = v; else g_pad_y[t] = v;
}

// ---------------- zero accumulators ----------------
__global__ void zero_kernel() {
    const int total = (PP+1)*LTOT;
    for (int t = blockIdx.x*blockDim.x + threadIdx.x; t < total; t += gridDim.x*blockDim.x) {
        if (t < PP*LTOT) g_xsum[t] = 0.f; else g_wsum[t - PP*LTOT] = 0.f;
    }
}

// ---------------- block matching: one block per center ----------------
// dist(t) = sum over 7x7 of (pad[4ci+o0+di, 4cj+o1+dj] - pad[4ci+18+di, 4cj+18+dj])^2
// select M smallest with (dist, index) lexicographic order (matches stable top_k).
template<int M, bool USE_X>
__global__ __launch_bounds__(256) void bm_kernel() {
    __shared__ float win[43*43];
    __shared__ float dist[NOFF];
    __shared__ float rv[256];
    __shared__ int   ri[256];
    const float* pad = USE_X ? g_pad_x : g_pad_y;
    int* idx_out = (M == M1) ? g_idx1 : g_idx2;

    int ci = blockIdx.x >> 6, cj = blockIdx.x & 63;
    int r0 = 4*ci, c0 = 4*cj;               // window top-left in padded coords

    for (int t = threadIdx.x; t < 43*43; t += 256)
        win[t] = pad[(r0 + t/43)*HP + (c0 + t%43)];
    __syncthreads();

    float cp[PP];
#pragma unroll
    for (int d = 0; d < PP; ++d) cp[d] = win[(INC + d/7)*43 + (INC + d%7)];

    for (int t = threadIdx.x; t < NOFF; t += 256) {
        int o0 = t / WN, o1 = t % WN;
        const float* w0 = &win[o0*43 + o1];
        float s = 0.f;
#pragma unroll
        for (int d = 0; d < PP; ++d) {
            float df = w0[(d/7)*43 + (d%7)] - cp[d];
            s = fmaf(df, df, s);
        }
        dist[t] = (t == CENTER_OFF) ? -1.f : s;
    }
    __syncthreads();

    const float BIG = 3.0e38f;
    for (int k = 0; k < M; ++k) {
        float bv = BIG; int bi = NOFF;
        for (int t = threadIdx.x; t < NOFF; t += 256) {
            float v = dist[t];
            if (v < bv) { bv = v; bi = t; }     // ascending t => stable on ties
        }
        rv[threadIdx.x] = bv; ri[threadIdx.x] = bi;
        __syncthreads();
        if (threadIdx.x < 32) {
            float mv = rv[threadIdx.x]; int mi = ri[threadIdx.x];
#pragma unroll
            for (int s = 1; s < 8; ++s) {
                float ov = rv[threadIdx.x + 32*s]; int oi = ri[threadIdx.x + 32*s];
                if (ov < mv || (ov == mv && oi < mi)) { mv = ov; mi = oi; }
            }
#pragma unroll
            for (int off = 16; off > 0; off >>= 1) {
                float ov = __shfl_down_sync(0xffffffffu, mv, off);
                int   oi = __shfl_down_sync(0xffffffffu, mi, off);
                if (ov < mv || (ov == mv && oi < mi)) { mv = ov; mi = oi; }
            }
            if (threadIdx.x == 0) {
                dist[mi] = BIG;   // remove
                idx_out[blockIdx.x*M + k] = (r0 + mi/WN)*PG + (c0 + mi%WN);
            }
        }
        __syncthreads();
    }
}

// ---------------- batched denoise: one block per group ----------------
// A = G*G^T (+ c*I if ADDC).  theta = I - c*inv(A).
// Xh = theta*Y ; wts_k = 1/sum_j theta_kj^2 ; scatter Xh*w and w.
template<int M, bool ADDC, bool GUIDE_X, int NT>
__global__ __launch_bounds__(NT) void denoise_kernel(const float* __restrict__ sigma_p) {
    __shared__ float Gs[M*PP];        // guide patches, later reused for Y data
    __shared__ float A [M*M];
    __shared__ float Ai[M*(M+1)];
    __shared__ float wrow[M];
    __shared__ int   fidx[M];

    const int tid = threadIdx.x;
    const int b   = blockIdx.x;
    const int* idx = (M == M1) ? g_idx1 : g_idx2;
    const float* gpad = GUIDE_X ? g_pad_x : g_pad_y;
    float sg = *sigma_p;
    float c  = (float)PP * sg * sg;

    if (tid < M) fidx[tid] = idx[b*M + tid];
    __syncthreads();

    // gather guide patches
    for (int t = tid; t < M*PP; t += NT) {
        int k = t / PP, d = t % PP;
        int f = fidx[k]; int r = f / PG, cc = f % PG;
        Gs[t] = gpad[(r + d/7)*HP + (cc + d%7)];
    }
    __syncthreads();

    // A = Gs Gs^T (+cI)
    for (int t = tid; t < M*M; t += NT) {
        int a0 = t / M, b0 = t % M;
        const float* ra = &Gs[a0*PP];
        const float* rb = &Gs[b0*PP];
        float s = 0.f;
#pragma unroll 7
        for (int d = 0; d < PP; ++d) s = fmaf(ra[d], rb[d], s);
        if (ADDC && a0 == b0) s += c;
        A[t] = s;
    }
    __syncthreads();

    // reload data (Y) patches into Gs (safe: A already built)
    for (int t = tid; t < M*PP; t += NT) {
        int k = t / PP, d = t % PP;
        int f = fidx[k]; int r = f / PG, cc = f % PG;
        Gs[t] = g_pad_y[(r + d/7)*HP + (cc + d%7)];
    }

    // Cholesky (lower) in place
    for (int k = 0; k < M; ++k) {
        __syncthreads();
        if (tid == 0) A[k*M+k] = sqrtf(A[k*M+k]);
        __syncthreads();
        float dk = A[k*M+k];
        for (int r = k+1+tid; r < M; r += NT) A[r*M+k] /= dk;
        __syncthreads();
        int w = M-1-k;
        for (int t = tid; t < w*w; t += NT) {
            int r = k+1 + t / w, cc2 = k+1 + t % w;
            if (cc2 <= r) A[r*M+cc2] -= A[r*M+k]*A[cc2*M+k];
        }
    }
    __syncthreads();

    // Ai = inv(A) via two triangular solves, one column per thread
    if (tid < M) {
        const int col = tid;
        const int ST = M+1;
        // forward: L y = e_col   (y_i = 0 for i<col falls out naturally)
        for (int i = 0; i < M; ++i) {
            float s0=0.f, s1=0.f, s2=0.f, s3=0.f;
            int j = 0;
            for (; j+4 <= i; j += 4) {
                s0 = fmaf(A[i*M+j  ], Ai[(j  )*ST+col], s0);
                s1 = fmaf(A[i*M+j+1], Ai[(j+1)*ST+col], s1);
                s2 = fmaf(A[i*M+j+2], Ai[(j+2)*ST+col], s2);
                s3 = fmaf(A[i*M+j+3], Ai[(j+3)*ST+col], s3);
            }
            for (; j < i; ++j) s0 = fmaf(A[i*M+j], Ai[j*ST+col], s0);
            float s = ((i == col) ? 1.f : 0.f) - ((s0+s1) + (s2+s3));
            Ai[i*ST+col] = s / A[i*M+i];
        }
        // backward: L^T z = y  (in place)
        for (int i = M-1; i >= 0; --i) {
            float s0=0.f, s1=0.f, s2=0.f, s3=0.f;
            int j = i+1;
            for (; j+4 <= M; j += 4) {
                s0 = fmaf(A[(j  )*M+i], Ai[(j  )*ST+col], s0);
                s1 = fmaf(A[(j+1)*M+i], Ai[(j+1)*ST+col], s1);
                s2 = fmaf(A[(j+2)*M+i], Ai[(j+2)*ST+col], s2);
                s3 = fmaf(A[(j+3)*M+i], Ai[(j+3)*ST+col], s3);
            }
            for (; j < M; ++j) s0 = fmaf(A[j*M+i], Ai[j*ST+col], s0);
            float s = Ai[i*ST+col] - ((s0+s1) + (s2+s3));
            Ai[i*ST+col] = s / A[i*M+i];
        }
    }
    __syncthreads();

    // weights: 1 / sum_j (delta_kj - c*Ai_kj)^2
    for (int k = tid; k < M; k += NT) {
        float s = 0.f;
        for (int j = 0; j < M; ++j) {
            float th = ((j == k) ? 1.f : 0.f) - c*Ai[k*(M+1)+j];
            s = fmaf(th, th, s);
        }
        wrow[k] = 1.f / s;
    }
    __syncthreads();

    // Xh = Y - c*(Ai*Y); scatter Xh*w into xsum and w into wsum
    for (int t = tid; t < M*PP; t += NT) {
        int k = t / PP, d = t % PP;
        float s = 0.f;
        const float* arow = &Ai[k*(M+1)];
        for (int j = 0; j < M; ++j) s = fmaf(arow[j], Gs[j*PP+d], s);
        float xh = Gs[k*PP+d] - c*s;
        atomicAdd(&g_xsum[d*LTOT + fidx[k]], xh * wrow[k]);
    }
    for (int k = tid; k < M; k += NT)
        atomicAdd(&g_wsum[fidx[k]], wrow[k]);
}

// ---------------- fold + normalize + crop ----------------
__global__ void fold_kernel(float* __restrict__ out, int to_den1) {
    int t = blockIdx.x*blockDim.x + threadIdx.x;
    if (t >= IMG*IMG) return;
    int y = t >> 8, x = t & 255;
    float num = 0.f, den = 0.f;
#pragma unroll
    for (int i = 0; i < 7; ++i) {
        int base = (y + RPAD - i)*PG + (x + RPAD);
#pragma unroll
        for (int j = 0; j < 7; ++j) {
            int f = base - j;
            num += g_xsum[(i*7+j)*LTOT + f];
            den += g_wsum[f];
        }
    }
    float v = num / den;
    if (to_den1) g_den1[t] = v; else out[t] = v;
}

// ---------------- launch ----------------
extern "C" void kernel_launch(void* const* d_in, const int* in_sizes, int n_in,
                              void* d_out, int out_size) {
    const float* y   = (const float*)d_in[0];
    const float* sig = (const float*)d_in[1];
    float* out = (float*)d_out;

    const int PADB = (HP*HP + 255)/256;

    // ---- pass 1 (p=7, m=18) ----
    pad_input_kernel<<<PADB, 256>>>(y, 0);
    bm_kernel<M1, false><<<NC, 256>>>();
    zero_kernel<<<4096, 256>>>();
    denoise_kernel<M1, false, false, 128><<<NC, 128>>>(sig);
    fold_kernel<<<(IMG*IMG+255)/256, 256>>>(nullptr, 1);

    // ---- pass 2 (p=7, m=55) ----
    pad_input_kernel<<<PADB, 256>>>(y, 1);
    bm_kernel<M2, true><<<NC, 256>>>();
    zero_kernel<<<4096, 256>>>();
    denoise_kernel<M2, true, true, 256><<<NC, 256>>>(sig);
    fold_kernel<<<(IMG*IMG+255)/256, 256>>>(out, 0);
}

// round 2
// speedup vs baseline: 1.5407x; 1.5407x over previous
#include <cuda_runtime.h>
#include <math.h>

// ---------------- problem constants ----------------
#define IMG   256
#define PP    49           // patch pixels (7x7)
#define WN    37           // search window
#define NOFF  (WN*WN)      // 1369
#define INC   18           // WN/2
#define RPAD  21           // PATCH/2 + WN/2
#define HP    298          // IMG + 2*RPAD
#define PG    292          // patch-grid size = IMG + WN - 1
#define LTOT  (PG*PG)      // 85264
#define NC    4096         // total centers (64x64)
#define M1    18
#define M2    55
#define CENTER_OFF (INC*WN + INC)   // 684
#define PPAD  52           // padded patch stride (multiple of 4)

// ---------------- device scratch ----------------
__device__ float g_pad_y[HP*HP];
__device__ float g_pad_x[HP*HP];
__device__ float g_den1[IMG*IMG];
__device__ int   g_idx1[NC*M1];
__device__ int   g_idx2[NC*M2];
__device__ float g_xsum[PP*LTOT];
__device__ float g_wsum[LTOT];

// ---------------- reflect pad 256 -> 298 ----------------
__global__ void pad_input_kernel(const float* __restrict__ src, int use_den1) {
    int t = blockIdx.x * blockDim.x + threadIdx.x;
    if (t >= HP*HP) return;
    int y = t / HP - RPAD, x = t % HP - RPAD;
    y = (y < 0) ? -y : ((y > IMG-1) ? 2*(IMG-1) - y : y);
    x = (x < 0) ? -x : ((x > IMG-1) ? 2*(IMG-1) - x : x);
    float v = use_den1 ? g_den1[y*IMG + x] : src[y*IMG + x];
    if (use_den1) g_pad_x[t] = v; else g_pad_y[t] = v;
}

// ---------------- zero accumulators ----------------
__global__ void zero_kernel() {
    const int total = (PP+1)*LTOT;
    for (int t = blockIdx.x*blockDim.x + threadIdx.x; t < total; t += gridDim.x*blockDim.x) {
        if (t < PP*LTOT) g_xsum[t] = 0.f; else g_wsum[t - PP*LTOT] = 0.f;
    }
}

// ---------------- block matching via exact radix select ----------------
// key = (ordered_dist_bits << 16) | offset_index  -> 48-bit unique keys.
// select M smallest keys: identical set+tie-order as stable lax.top_k.
template<int M, bool USE_X>
__global__ __launch_bounds__(256) void bm_kernel() {
    __shared__ float win[43*43];
    __shared__ unsigned int hist[256];
    __shared__ unsigned int wsum[8];
    __shared__ unsigned int s_selbin, s_need, s_cnt;

    const float* pad = USE_X ? g_pad_x : g_pad_y;
    int* idx_out = (M == M1) ? g_idx1 : g_idx2;

    const int tid = threadIdx.x;
    const int ci = blockIdx.x >> 6, cj = blockIdx.x & 63;
    const int r0 = 4*ci, c0 = 4*cj;

    for (int t = tid; t < 43*43; t += 256)
        win[t] = pad[(r0 + t/43)*HP + (c0 + t%43)];
    __syncthreads();

    float cp[PP];
#pragma unroll
    for (int d = 0; d < PP; ++d) cp[d] = win[(INC + d/7)*43 + (INC + d%7)];

    unsigned long long key[6];
#pragma unroll
    for (int q = 0; q < 6; ++q) {
        int t = tid + 256*q;
        if (t < NOFF) {
            int o0 = t / WN, o1 = t % WN;
            const float* w0 = &win[o0*43 + o1];
            float s = 0.f;
#pragma unroll
            for (int d = 0; d < PP; ++d) {
                float df = w0[(d/7)*43 + (d%7)] - cp[d];
                s = fmaf(df, df, s);
            }
            unsigned int u = __float_as_uint(s) | 0x80000000u;
            if (t == CENTER_OFF) u = 0u;
            key[q] = ((unsigned long long)u << 16) | (unsigned int)t;
        } else {
            key[q] = ~0ull;
        }
    }

    // 6-pass MSB radix select for the M-th smallest key
    unsigned long long prefix = 0ull;
    unsigned int need = M;
#pragma unroll 1
    for (int pass = 0; pass < 6; ++pass) {
        int shift = 40 - 8*pass;
        hist[tid] = 0;
        __syncthreads();
#pragma unroll
        for (int q = 0; q < 6; ++q) {
            if (key[q] != ~0ull && (key[q] >> (shift + 8)) == prefix)
                atomicAdd(&hist[(unsigned int)(key[q] >> shift) & 255u], 1u);
        }
        __syncthreads();
        unsigned int h = hist[tid];
        unsigned int v = h;
#pragma unroll
        for (int o = 1; o < 32; o <<= 1) {
            unsigned int n = __shfl_up_sync(0xffffffffu, v, o);
            if ((tid & 31) >= o) v += n;
        }
        if ((tid & 31) == 31) wsum[tid >> 5] = v;
        __syncthreads();
        if (tid < 8) {
            unsigned int w = wsum[tid];
            unsigned int x = w;
#pragma unroll
            for (int o = 1; o < 8; o <<= 1) {
                unsigned int n = __shfl_up_sync(0xffu, x, o);
                if (tid >= o) x += n;
            }
            wsum[tid] = x - w;   // exclusive
        }
        __syncthreads();
        unsigned int excl = v - h + wsum[tid >> 5];
        if (excl < need && need <= excl + h) {
            s_selbin = (unsigned int)tid;
            s_need   = need - excl;
        }
        __syncthreads();
        prefix = (prefix << 8) | (unsigned long long)s_selbin;
        need = s_need;
    }
    // prefix == K, the M-th smallest key. Emit all keys <= K.
    if (tid == 0) s_cnt = 0;
    __syncthreads();
#pragma unroll
    for (int q = 0; q < 6; ++q) {
        if (key[q] <= prefix) {   // invalid keys are ~0 > K
            unsigned int pos = atomicAdd(&s_cnt, 1u);
            int t = (int)(key[q] & 0xffffu);
            int o0 = t / WN, o1 = t % WN;
            idx_out[blockIdx.x*M + pos] = (r0 + o0)*PG + (c0 + o1);
        }
    }
}

// ---------------- batched denoise: one block per group ----------------
// A = G G^T (+cI). theta = I - c*inv(A). Inverse via in-place Gauss-Jordan (SPD).
// Xh = Y - c*(Ainv*Y); wts_k = 1/||theta_k||^2; scatter Xh*w and w.
template<int M, int S, bool ADDC, bool GUIDE_X, bool RELOAD, int NT>
__global__ __launch_bounds__(NT) void denoise_kernel(const float* __restrict__ sigma_p) {
    __shared__ __align__(16) float Gs[M*PPAD];
    __shared__ __align__(16) float A [M*S];
    __shared__ __align__(16) float rowk[S];
    __shared__ float colk[M];
    __shared__ float wrow[M];
    __shared__ int   fidx[M];

    const int tid = threadIdx.x;
    const int b   = blockIdx.x;
    const int* idx = (M == M1) ? g_idx1 : g_idx2;
    const float* gpad = GUIDE_X ? g_pad_x : g_pad_y;
    const float sg = *sigma_p;
    const float c  = (float)PP * sg * sg;

    if (tid < M) fidx[tid] = idx[b*M + tid];
    if (tid < S) rowk[tid] = 0.f;   // zero pads once; [M,S) never rewritten
    __syncthreads();

    // gather guide patches (zero pad columns)
    for (int t = tid; t < M*PPAD; t += NT) {
        int k = t / PPAD, col = t % PPAD;
        float v = 0.f;
        if (col < PP) {
            int f = fidx[k]; int r = f / PG, cc = f % PG;
            v = gpad[(r + col/7)*HP + (cc + col%7)];
        }
        Gs[t] = v;
    }
    __syncthreads();

    // A = Gs Gs^T (+cI): lower triangle, mirrored. float4 dot over padded rows.
    const int T = M*(M+1)/2;
    for (int t = tid; t < T; t += NT) {
        int a0 = (int)((sqrtf(8.0f*(float)t + 1.0f) - 1.0f)*0.5f);
        while ((a0+1)*(a0+2)/2 <= t) ++a0;
        while (a0*(a0+1)/2 > t) --a0;
        int b0 = t - a0*(a0+1)/2;
        const float4* ra = (const float4*)(Gs + a0*PPAD);
        const float4* rb = (const float4*)(Gs + b0*PPAD);
        float s = 0.f;
#pragma unroll
        for (int g = 0; g < PPAD/4; ++g) {
            float4 x = ra[g], y = rb[g];
            s = fmaf(x.x, y.x, s); s = fmaf(x.y, y.y, s);
            s = fmaf(x.z, y.z, s); s = fmaf(x.w, y.w, s);
        }
        if (ADDC && a0 == b0) s += c;
        A[a0*S + b0] = s;
        A[b0*S + a0] = s;
    }
    __syncthreads();

    // reload data (Y) patches if guide != Y
    if (RELOAD) {
        for (int t = tid; t < M*PPAD; t += NT) {
            int k = t / PPAD, col = t % PPAD;
            float v = 0.f;
            if (col < PP) {
                int f = fidx[k]; int r = f / PG, cc = f % PG;
                v = g_pad_y[(r + col/7)*HP + (cc + col%7)];
            }
            Gs[t] = v;
        }
    }

    // in-place Gauss-Jordan inverse (no pivoting; A is SPD)
#pragma unroll 1
    for (int k = 0; k < M; ++k) {
        __syncthreads();
        float dinv = 1.0f / A[k*S + k];
        for (int t = tid; t < M; t += NT) {
            colk[t] = A[t*S + k];
            float rv = A[k*S + t] * dinv;
            if (t == k) rv = dinv;
            rowk[t] = rv;
        }
        __syncthreads();
        for (int t = tid; t < M*(S/4); t += NT) {
            int i = t / (S/4), g = t % (S/4);
            float4 r4 = ((const float4*)rowk)[g];
            float4* ap = (float4*)(A + i*S) + g;
            if (i == k) {
                *ap = r4;
            } else {
                float ci = colk[i];
                float4 a4 = *ap;
                int j0 = g*4;
                a4.x = (j0+0 == k) ? -ci*dinv : fmaf(-ci, r4.x, a4.x);
                a4.y = (j0+1 == k) ? -ci*dinv : fmaf(-ci, r4.y, a4.y);
                a4.z = (j0+2 == k) ? -ci*dinv : fmaf(-ci, r4.z, a4.z);
                a4.w = (j0+3 == k) ? -ci*dinv : fmaf(-ci, r4.w, a4.w);
                *ap = a4;
            }
        }
    }
    __syncthreads();

    // weights: 1 / sum_j (delta_kj - c*Ainv_kj)^2
    for (int k = tid; k < M; k += NT) {
        float s = 0.f;
        for (int j = 0; j < M; ++j) {
            float th = ((j == k) ? 1.f : 0.f) - c*A[k*S + j];
            s = fmaf(th, th, s);
        }
        wrow[k] = 1.f / s;
    }
    __syncthreads();

    // Xh = Y - c*(Ainv*Y); scatter Xh*w and w
    for (int t = tid; t < M*(PPAD/4); t += NT) {
        int k = t / (PPAD/4), g = t % (PPAD/4);
        const float4* Yg = (const float4*)Gs + g;
        float4 s = make_float4(0.f, 0.f, 0.f, 0.f);
        const float* arow = A + k*S;
        for (int j = 0; j < M; ++j) {
            float a = arow[j];
            float4 y4 = Yg[j*(PPAD/4)];
            s.x = fmaf(a, y4.x, s.x); s.y = fmaf(a, y4.y, s.y);
            s.z = fmaf(a, y4.z, s.z); s.w = fmaf(a, y4.w, s.w);
        }
        float4 yk = ((const float4*)(Gs + k*PPAD))[g];
        float w = wrow[k];
        int f = fidx[k];
        int d0 = g*4;
        float xh;
        xh = (yk.x - c*s.x)*w; if (d0+0 < PP) atomicAdd(&g_xsum[(d0+0)*LTOT + f], xh);
        xh = (yk.y - c*s.y)*w; if (d0+1 < PP) atomicAdd(&g_xsum[(d0+1)*LTOT + f], xh);
        xh = (yk.z - c*s.z)*w; if (d0+2 < PP) atomicAdd(&g_xsum[(d0+2)*LTOT + f], xh);
        xh = (yk.w - c*s.w)*w; if (d0+3 < PP) atomicAdd(&g_xsum[(d0+3)*LTOT + f], xh);
    }
    for (int k = tid; k < M; k += NT)
        atomicAdd(&g_wsum[fidx[k]], wrow[k]);
}

// ---------------- fold + normalize + crop ----------------
__global__ void fold_kernel(float* __restrict__ out, int to_den1) {
    int t = blockIdx.x*blockDim.x + threadIdx.x;
    if (t >= IMG*IMG) return;
    int y = t >> 8, x = t & 255;
    float num = 0.f, den = 0.f;
#pragma unroll
    for (int i = 0; i < 7; ++i) {
        int base = (y + RPAD - i)*PG + (x + RPAD);
#pragma unroll
        for (int j = 0; j < 7; ++j) {
            int f = base - j;
            num += g_xsum[(i*7+j)*LTOT + f];
            den += g_wsum[f];
        }
    }
    float v = num / den;
    if (to_den1) g_den1[t] = v; else out[t] = v;
}

// ---------------- launch ----------------
extern "C" void kernel_launch(void* const* d_in, const int* in_sizes, int n_in,
                              void* d_out, int out_size) {
    const float* y   = (const float*)d_in[0];
    const float* sig = (const float*)d_in[1];
    float* out = (float*)d_out;

    const int PADB = (HP*HP + 255)/256;

    // ---- pass 1 (p=7, m=18) ----
    pad_input_kernel<<<PADB, 256>>>(y, 0);
    bm_kernel<M1, false><<<NC, 256>>>();
    zero_kernel<<<2048, 256>>>();
    denoise_kernel<M1, 20, false, false, false, 128><<<NC, 128>>>(sig);
    fold_kernel<<<(IMG*IMG+255)/256, 256>>>(nullptr, 1);

    // ---- pass 2 (p=7, m=55) ----
    pad_input_kernel<<<PADB, 256>>>(y, 1);
    bm_kernel<M2, true><<<NC, 256>>>();
    zero_kernel<<<2048, 256>>>();
    denoise_kernel<M2, 56, true, true, true, 256><<<NC, 256>>>(sig);
    fold_kernel<<<(IMG*IMG+255)/256, 256>>>(out, 0);
}